// round 10
// baseline (speedup 1.0000x reference)
#include <cuda_runtime.h>

#define NN 100000
#define FD 32

// Scratch (static device globals — no allocation in kernel_launch)
__device__ float g_msgA[NN * FD];   // layer-0 messages
__device__ float g_msgB[NN * FD];   // layer-1 messages
__device__ int   g_csr[2000000];    // CSR src indices (E <= 1.6M + headroom)
__device__ int   g_row[NN];         // CSR row starts
__device__ int   g_cur[NN];         // fill cursors
__device__ int   g_cnt[NN];         // in-degree (no self-loop)
__device__ float g_dinv[NN];
__device__ int   g_total;

__global__ void k_zero() {
    int i = blockIdx.x * blockDim.x + threadIdx.x;
    if (i < NN) g_cnt[i] = 0;
    if (i == 0) g_total = 0;
}

__global__ void k_count(const int* __restrict__ dst, int E) {
    int t = blockIdx.x * blockDim.x + threadIdx.x;
    int e = t * 4;
    if (e + 3 < E) {
        int4 d = *reinterpret_cast<const int4*>(dst + e);
        atomicAdd(&g_cnt[d.x], 1);
        atomicAdd(&g_cnt[d.y], 1);
        atomicAdd(&g_cnt[d.z], 1);
        atomicAdd(&g_cnt[d.w], 1);
    } else {
        for (int i = e; i < E; i++) atomicAdd(&g_cnt[dst[i]], 1);
    }
}

// Per-block exclusive scan + one atomicAdd for the block base.
// Block bases are assignment-order-dependent but each node still gets a
// private contiguous range of length cnt[i] -> gather stays correct.
__global__ __launch_bounds__(256) void k_alloc() {
    __shared__ int sh[256];
    __shared__ int base;
    int tid = threadIdx.x;
    int i = blockIdx.x * 256 + tid;
    int c = (i < NN) ? g_cnt[i] : 0;
    sh[tid] = c;
    __syncthreads();
    #pragma unroll
    for (int off = 1; off < 256; off <<= 1) {
        int t = (tid >= off) ? sh[tid - off] : 0;
        __syncthreads();
        sh[tid] += t;
        __syncthreads();
    }
    if (tid == 255) base = atomicAdd(&g_total, sh[255]);
    __syncthreads();
    if (i < NN) {
        int start = base + sh[tid] - c;
        g_row[i] = start;
        g_cur[i] = start;
    }
}

__global__ void k_fill(const int* __restrict__ src,
                       const int* __restrict__ dst, int E) {
    int t = blockIdx.x * blockDim.x + threadIdx.x;
    int e = t * 4;
    if (e + 3 < E) {
        int4 s = *reinterpret_cast<const int4*>(src + e);
        int4 d = *reinterpret_cast<const int4*>(dst + e);
        g_csr[atomicAdd(&g_cur[d.x], 1)] = s.x;
        g_csr[atomicAdd(&g_cur[d.y], 1)] = s.y;
        g_csr[atomicAdd(&g_cur[d.z], 1)] = s.z;
        g_csr[atomicAdd(&g_cur[d.w], 1)] = s.w;
    } else {
        for (int i = e; i < E; i++)
            g_csr[atomicAdd(&g_cur[dst[i]], 1)] = src[i];
    }
}

// msg0 = dinv * x  (GCN linearity: W0 applied after aggregation).
// dinv computed inline from cnt (+1 self-loop).
__global__ void k_scale0(const float* __restrict__ x) {
    int g = blockIdx.x * blockDim.x + threadIdx.x;   // one float4 per thread
    if (g >= NN * FD / 4) return;
    int node = g >> 3;
    float dv = rsqrtf((float)(__ldg(&g_cnt[node]) + 1));
    if ((g & 7) == 0) g_dinv[node] = dv;
    float4 v = *reinterpret_cast<const float4*>(x + (size_t)g * 4);
    v.x *= dv; v.y *= dv; v.z *= dv; v.w *= dv;
    *reinterpret_cast<float4*>(g_msgA + (size_t)g * 4) = v;
}

// Warp-per-node gather with staged indices + MLP=8 gather batches, then
// fused GEMV: ph = dinv*(self + sum msgA[src]); msgB = dinv*relu(ph@W0+b0).
__global__ __launch_bounds__(256) void k_gmid(const float* __restrict__ W0,
                                              const float* __restrict__ b0) {
    __shared__ float Ws[FD * FD];
    __shared__ float s_row[8][FD];
    int tid = threadIdx.x;
    int lane = tid & 31;
    int wb = tid >> 5;
    #pragma unroll
    for (int i = tid; i < FD * FD; i += 256) Ws[i] = W0[i];
    __syncthreads();

    float Wc[FD];
    #pragma unroll
    for (int k = 0; k < FD; k++) Wc[k] = Ws[k * FD + lane];
    float bl = b0[lane];

    int node = blockIdx.x * 8 + wb;          // grid = NN/8 exactly
    int start = g_row[node];
    int d = g_cnt[node];
    float dv = g_dinv[node];

    float acc = g_msgA[(size_t)node * FD + lane];   // self-loop term

    for (int c = 0; c < d; c += 32) {
        int rem = d - c; if (rem > 32) rem = 32;
        // stage up to 32 indices with ONE coalesced load
        int idx = (lane < rem) ? g_csr[start + c + lane] : 0;
        for (int k = 0; k < rem; k += 8) {           // uniform trip count
            float a[8];
            #pragma unroll
            for (int j = 0; j < 8; j++) {            // 8 independent gathers
                int s = __shfl_sync(0xffffffffu, idx, k + j);
                a[j] = (k + j < rem) ? g_msgA[(size_t)s * FD + lane] : 0.0f;
            }
            acc += ((a[0] + a[1]) + (a[2] + a[3])) + ((a[4] + a[5]) + (a[6] + a[7]));
        }
    }

    s_row[wb][lane] = dv * acc;
    __syncwarp();
    const float4* r = reinterpret_cast<const float4*>(s_row[wb]);
    float o = 0.0f;
    #pragma unroll
    for (int j = 0; j < FD / 4; j++) {
        float4 t4 = r[j];                            // broadcast LDS.128
        o = fmaf(t4.x, Wc[4 * j + 0], o);
        o = fmaf(t4.y, Wc[4 * j + 1], o);
        o = fmaf(t4.z, Wc[4 * j + 2], o);
        o = fmaf(t4.w, Wc[4 * j + 3], o);
    }
    __syncwarp();
    g_msgB[(size_t)node * FD + lane] = dv * fmaxf(o + bl, 0.0f);
}

// Same gather; fused double GEMV:
//   ph = dinv*(self+sum); h2 = relu(ph@W1+b1); out = h2@Wf+bf
__global__ __launch_bounds__(256) void k_gfinal(const float* __restrict__ W1,
                                                const float* __restrict__ b1,
                                                const float* __restrict__ Wf,
                                                const float* __restrict__ bf,
                                                float* __restrict__ out) {
    __shared__ float Ws1[FD * FD];
    __shared__ float Wsf[FD * FD];
    __shared__ float s_row[8][FD];
    int tid = threadIdx.x;
    int lane = tid & 31;
    int wb = tid >> 5;
    #pragma unroll
    for (int i = tid; i < FD * FD; i += 256) { Ws1[i] = W1[i]; Wsf[i] = Wf[i]; }
    __syncthreads();

    float Wc1[FD];
    #pragma unroll
    for (int k = 0; k < FD; k++) Wc1[k] = Ws1[k * FD + lane];
    float b1l = b1[lane];
    float bfl = bf[lane];

    int node = blockIdx.x * 8 + wb;
    int start = g_row[node];
    int d = g_cnt[node];
    float dv = g_dinv[node];

    float acc = g_msgB[(size_t)node * FD + lane];

    for (int c = 0; c < d; c += 32) {
        int rem = d - c; if (rem > 32) rem = 32;
        int idx = (lane < rem) ? g_csr[start + c + lane] : 0;
        for (int k = 0; k < rem; k += 8) {
            float a[8];
            #pragma unroll
            for (int j = 0; j < 8; j++) {
                int s = __shfl_sync(0xffffffffu, idx, k + j);
                a[j] = (k + j < rem) ? g_msgB[(size_t)s * FD + lane] : 0.0f;
            }
            acc += ((a[0] + a[1]) + (a[2] + a[3])) + ((a[4] + a[5]) + (a[6] + a[7]));
        }
    }

    s_row[wb][lane] = dv * acc;
    __syncwarp();
    const float4* r = reinterpret_cast<const float4*>(s_row[wb]);
    float o1 = 0.0f;
    #pragma unroll
    for (int j = 0; j < FD / 4; j++) {
        float4 t4 = r[j];
        o1 = fmaf(t4.x, Wc1[4 * j + 0], o1);
        o1 = fmaf(t4.y, Wc1[4 * j + 1], o1);
        o1 = fmaf(t4.z, Wc1[4 * j + 2], o1);
        o1 = fmaf(t4.w, Wc1[4 * j + 3], o1);
    }
    __syncwarp();
    float h2 = fmaxf(o1 + b1l, 0.0f);
    s_row[wb][lane] = h2;
    __syncwarp();
    float o2 = bfl;
    #pragma unroll
    for (int j = 0; j < FD / 4; j++) {
        float4 t4 = r[j];
        // Wf read from shared (keeps regs ~70 -> 3 blocks/SM)
        o2 = fmaf(t4.x, Wsf[(4 * j + 0) * FD + lane], o2);
        o2 = fmaf(t4.y, Wsf[(4 * j + 1) * FD + lane], o2);
        o2 = fmaf(t4.z, Wsf[(4 * j + 2) * FD + lane], o2);
        o2 = fmaf(t4.w, Wsf[(4 * j + 3) * FD + lane], o2);
    }
    __syncwarp();
    out[(size_t)node * FD + lane] = o2;
}

extern "C" void kernel_launch(void* const* d_in, const int* in_sizes, int n_in,
                              void* d_out, int out_size) {
    const float* x   = (const float*)d_in[0];
    const int*   ei  = (const int*)d_in[1];   // JAX x64 disabled -> int32
    const float* W0  = (const float*)d_in[2];
    const float* b0  = (const float*)d_in[3];
    const float* W1  = (const float*)d_in[4];
    const float* b1  = (const float*)d_in[5];
    const float* Wf  = (const float*)d_in[6];
    const float* bf  = (const float*)d_in[7];
    float* out = (float*)d_out;

    int E = in_sizes[1] / 2;          // edge_index is [2, E]
    const int* src = ei;
    const int* dst = ei + E;

    int nb_n  = (NN + 255) / 256;
    int nb_c  = ((E + 3) / 4 + 255) / 256;
    int nb_s0 = (NN * FD / 4 + 255) / 256;
    int nb_g  = NN / 8;               // one warp per node, 8 warps/block

    // CSR build + normalization
    k_zero<<<nb_n, 256>>>();
    k_count<<<nb_c, 256>>>(dst, E);
    k_alloc<<<nb_n, 256>>>();
    k_fill<<<nb_c, 256>>>(src, dst, E);

    // layer 0 messages (dinv fused)
    k_scale0<<<nb_s0, 256>>>(x);

    // layer 0 aggregate + W0/relu fused -> layer 1 messages
    k_gmid<<<nb_g, 256>>>(W0, b0);

    // layer 1 aggregate + W1/relu + Wf fused -> output
    k_gfinal<<<nb_g, 256>>>(W1, b1, Wf, bf, out);
}

// round 11
// speedup vs baseline: 1.8847x; 1.8847x over previous
#include <cuda_runtime.h>
#include <cuda_fp16.h>

#define NN 100000
#define FD 32
#define EPT 4   // edges per scatter thread

// Scratch (static device globals — no allocation in kernel_launch)
__device__ __half g_sc[NN * FD];    // messages (fp16), gather side
__device__ __half g_aggh[NN * FD];  // fp16 accumulator, seeded with self-loop
__device__ float  g_dinv[NN];
__device__ int    g_deg[NN];

__global__ void k_zero() {
    int i = blockIdx.x * blockDim.x + threadIdx.x;
    if (i < NN) g_deg[i] = 1;  // self-loop contributes 1
}

__global__ void k_count(const int* __restrict__ dst, int E) {
    int t = blockIdx.x * blockDim.x + threadIdx.x;
    int e = t * 4;
    if (e + 3 < E) {
        int4 d = *reinterpret_cast<const int4*>(dst + e);
        atomicAdd(&g_deg[d.x], 1);
        atomicAdd(&g_deg[d.y], 1);
        atomicAdd(&g_deg[d.z], 1);
        atomicAdd(&g_deg[d.w], 1);
    } else {
        for (int i = e; i < E; i++) atomicAdd(&g_deg[dst[i]], 1);
    }
}

// msg0 = fp16(dinv * x); seeds fp16 accumulator (self-loop folded);
// dinv computed inline.
__global__ void k_scale0(const float* __restrict__ x) {
    int g = blockIdx.x * blockDim.x + threadIdx.x;   // one float4 per thread
    if (g >= NN * FD / 4) return;
    int node = g >> 3;
    float dv = rsqrtf((float)g_deg[node]);
    if ((g & 7) == 0) g_dinv[node] = dv;
    float4 v = *reinterpret_cast<const float4*>(x + (size_t)g * 4);
    __half2 p0 = __floats2half2_rn(v.x * dv, v.y * dv);
    __half2 p1 = __floats2half2_rn(v.z * dv, v.w * dv);
    uint2 packed;
    packed.x = *reinterpret_cast<unsigned int*>(&p0);
    packed.y = *reinterpret_cast<unsigned int*>(&p1);
    *reinterpret_cast<uint2*>(g_sc   + (size_t)g * 4) = packed;
    *reinterpret_cast<uint2*>(g_aggh + (size_t)g * 4) = packed;
}

// Scatter: 4 lanes per edge (lane covers 8 fp16 features = 16B), EPT edges
// per thread batched (MLP). Raw-bit gather + fp16x2 vector RED: NO converts.
__global__ __launch_bounds__(256) void k_scatter(const int* __restrict__ src,
                                                 const int* __restrict__ dst,
                                                 int E) {
    long long t = (long long)blockIdx.x * 256 + threadIdx.x;
    int e0 = (int)(t >> 2) * EPT;
    if (e0 >= E) return;
    int q = ((int)t & 3) << 3;   // feature offset 0,8,16,24 (halves)

    int s[EPT], d[EPT];
    int n = (E - e0 < EPT) ? (E - e0) : EPT;
    #pragma unroll
    for (int k = 0; k < EPT; k++) {
        int e = (k < n) ? e0 + k : e0;
        s[k] = src[e];
        d[k] = dst[e];
    }
    uint4 v[EPT];
    #pragma unroll
    for (int k = 0; k < EPT; k++)
        v[k] = *reinterpret_cast<const uint4*>(g_sc + (size_t)s[k] * FD + q);

    #pragma unroll
    for (int k = 0; k < EPT; k++) {
        if (k < n) {
            __half* a = g_aggh + (size_t)d[k] * FD + q;
            asm volatile("red.global.add.noftz.v4.f16x2 [%0], {%1, %2, %3, %4};"
                         :: "l"(a), "r"(v[k].x), "r"(v[k].y), "r"(v[k].z), "r"(v[k].w)
                         : "memory");
        }
    }
}

// Mid: ph = dinv*agg0; h1 = relu(ph @ W0 + b0); msg1 = fp16(dinv*h1).
__global__ __launch_bounds__(256) void k_mid(const float* __restrict__ W0,
                                             const float* __restrict__ b0) {
    __shared__ float Ws[FD * FD];
    __shared__ float s_row[8][FD];
    int tid = threadIdx.x;
    int lane = tid & 31;
    int wb = tid >> 5;
    #pragma unroll
    for (int i = tid; i < FD * FD; i += 256) Ws[i] = W0[i];
    __syncthreads();

    float Wc[FD];
    #pragma unroll
    for (int k = 0; k < FD; k++) Wc[k] = Ws[k * FD + lane];
    float bl = b0[lane];

    int base = (blockIdx.x * 8 + wb) * 8;    // 8 nodes per warp
    if (base >= NN) return;

    __half vh[8];
    float dvv[8];
    #pragma unroll
    for (int u = 0; u < 8; u++) {            // batched loads, MLP=8
        vh[u]  = g_aggh[(size_t)(base + u) * FD + lane];
        dvv[u] = __ldg(&g_dinv[base + u]);
    }

    #pragma unroll
    for (int u = 0; u < 8; u++) {
        int node = base + u;
        s_row[wb][lane] = dvv[u] * __half2float(vh[u]);
        __syncwarp();
        const float4* r = reinterpret_cast<const float4*>(s_row[wb]);
        float acc = 0.0f;
        #pragma unroll
        for (int j = 0; j < FD / 4; j++) {
            float4 t4 = r[j];                // broadcast LDS.128
            acc = fmaf(t4.x, Wc[4 * j + 0], acc);
            acc = fmaf(t4.y, Wc[4 * j + 1], acc);
            acc = fmaf(t4.z, Wc[4 * j + 2], acc);
            acc = fmaf(t4.w, Wc[4 * j + 3], acc);
        }
        __syncwarp();
        __half s1 = __float2half(dvv[u] * fmaxf(acc + bl, 0.0f));
        g_sc[(size_t)node * FD + lane]   = s1;
        g_aggh[(size_t)node * FD + lane] = s1;
    }
}

// Final: ph = dinv*agg1; h2 = relu(ph @ W1 + b1); out = h2 @ Wf + bf.
__global__ __launch_bounds__(256) void k_final(const float* __restrict__ W1,
                                               const float* __restrict__ b1,
                                               const float* __restrict__ Wf,
                                               const float* __restrict__ bf,
                                               float* __restrict__ out) {
    __shared__ float Ws1[FD * FD];
    __shared__ float Wsf[FD * FD];
    __shared__ float s_row[8][FD];
    int tid = threadIdx.x;
    int lane = tid & 31;
    int wb = tid >> 5;
    #pragma unroll
    for (int i = tid; i < FD * FD; i += 256) { Ws1[i] = W1[i]; Wsf[i] = Wf[i]; }
    __syncthreads();

    float Wc1[FD];
    #pragma unroll
    for (int k = 0; k < FD; k++) Wc1[k] = Ws1[k * FD + lane];
    float b1l = b1[lane];
    float bfl = bf[lane];

    int base = (blockIdx.x * 8 + wb) * 8;
    if (base >= NN) return;

    __half vh[8];
    float dvv[8];
    #pragma unroll
    for (int u = 0; u < 8; u++) {
        vh[u]  = g_aggh[(size_t)(base + u) * FD + lane];
        dvv[u] = __ldg(&g_dinv[base + u]);
    }

    #pragma unroll
    for (int u = 0; u < 8; u++) {
        int node = base + u;
        s_row[wb][lane] = dvv[u] * __half2float(vh[u]);
        __syncwarp();
        const float4* r = reinterpret_cast<const float4*>(s_row[wb]);
        float o1 = 0.0f;
        #pragma unroll
        for (int j = 0; j < FD / 4; j++) {
            float4 t4 = r[j];
            o1 = fmaf(t4.x, Wc1[4 * j + 0], o1);
            o1 = fmaf(t4.y, Wc1[4 * j + 1], o1);
            o1 = fmaf(t4.z, Wc1[4 * j + 2], o1);
            o1 = fmaf(t4.w, Wc1[4 * j + 3], o1);
        }
        __syncwarp();
        float h2 = fmaxf(o1 + b1l, 0.0f);
        s_row[wb][lane] = h2;
        __syncwarp();
        float o2 = bfl;
        #pragma unroll
        for (int j = 0; j < FD / 4; j++) {
            float4 t4 = r[j];
            o2 = fmaf(t4.x, Wsf[(4 * j + 0) * FD + lane], o2);
            o2 = fmaf(t4.y, Wsf[(4 * j + 1) * FD + lane], o2);
            o2 = fmaf(t4.z, Wsf[(4 * j + 2) * FD + lane], o2);
            o2 = fmaf(t4.w, Wsf[(4 * j + 3) * FD + lane], o2);
        }
        __syncwarp();
        out[(size_t)node * FD + lane] = o2;
    }
}

extern "C" void kernel_launch(void* const* d_in, const int* in_sizes, int n_in,
                              void* d_out, int out_size) {
    const float* x   = (const float*)d_in[0];
    const int*   ei  = (const int*)d_in[1];   // JAX x64 disabled -> int32
    const float* W0  = (const float*)d_in[2];
    const float* b0  = (const float*)d_in[3];
    const float* W1  = (const float*)d_in[4];
    const float* b1  = (const float*)d_in[5];
    const float* Wf  = (const float*)d_in[6];
    const float* bf  = (const float*)d_in[7];
    float* out = (float*)d_out;

    int E = in_sizes[1] / 2;          // edge_index is [2, E]
    const int* src = ei;
    const int* dst = ei + E;

    int nb_n  = (NN + 255) / 256;
    int nb_c  = ((E + 3) / 4 + 255) / 256;
    int nb_s0 = (NN * FD / 4 + 255) / 256;
    int warps = NN / 8 / 8 * 8;                  // 12500 warps
    int nb_x  = (NN / 8 + 7) / 8;                // 1563 blocks (8 warps each)
    long long sthreads = (long long)((E + EPT - 1) / EPT) * 4;
    int nb_s  = (int)((sthreads + 255) / 256);
    (void)warps;

    // degree + normalization (dinv fused into scale0)
    k_zero<<<nb_n, 256>>>();
    k_count<<<nb_c, 256>>>(dst, E);

    // layer 0: scale only (W0 applied after aggregation)
    k_scale0<<<nb_s0, 256>>>(x);
    k_scatter<<<nb_s, 256>>>(src, dst, E);

    // mid: apply W0 + relu, produce layer-1 messages
    k_mid<<<nb_x, 256>>>(W0, b0);
    k_scatter<<<nb_s, 256>>>(src, dst, E);

    // final: apply W1 + relu, then Wf + bf
    k_final<<<nb_x, 256>>>(W1, b1, Wf, bf, out);
}